// round 6
// baseline (speedup 1.0000x reference)
#include <cuda_runtime.h>

#define B_   4
#define LQ_  128
#define LK_  256
#define D_   128
#define H_   128
#define NH_  8

#define L2E 1.4426950408889634f  // log2(e) for softmax exp

#define NSPLIT 16                // K-splits for the output projection

// ---- scratch (static device memory; no allocation) ----
__device__ __align__(16) float g_QH[B_*NH_*H_*LQ_];      // [b][n][h][q]
__device__ __align__(16) float g_KH[B_*NH_*H_*LK_];      // [b][n][h][k]
__device__ __align__(16) float g_ATTN[B_*NH_*LQ_*LK_];   // [b][n][q][k] softmax weights
__device__ __align__(16) float g_CONCAT[B_*LQ_*NH_*D_];  // [b][q][n*D+d]
__device__ __align__(16) float g_PART[NSPLIT*B_*LQ_*H_]; // split-K partials

// ============================================================================
// K1: merged Q+K per-head projections
// OUT[b][n][h][l] = sum_d W[n][h][d] * X[b][l][d]
// 32h x 64l tile, BK=16, 256 threads, thread = 2h x 4l.
// grid = (4, 4, 64); z<32 -> K-proj, z>=32 -> Q-proj (extra x-blocks exit).
// Active blocks: 32*4*4 (K) + 32*2*4 (Q) = 768.
// ============================================================================
__global__ void __launch_bounds__(256) proj_kernel(
    const float* __restrict__ Q, const float* __restrict__ K,
    const float* __restrict__ Wq, const float* __restrict__ Wk)
{
    int zz = blockIdx.z;
    bool isq = zz >= 32;
    int bn = isq ? (zz - 32) : zz;
    int b = bn >> 3, n = bn & 7;
    int L = isq ? LQ_ : LK_;
    int l0 = blockIdx.x * 64;
    if (l0 >= L) return;                        // uniform per block
    const float* X = isq ? Q : K;
    const float* W = isq ? Wq : Wk;
    float* OUT = isq ? g_QH : g_KH;

    __shared__ float Ws[16][32];   // [d][h] (scalar-read)
    __shared__ float Xs[16][64];   // [d][l] (float4-read, 256B rows)
    int h0 = blockIdx.y * 32;
    int tid = threadIdx.x;                 // 256
    int ty = tid >> 4, tx = tid & 15;      // 16 x 16; thread = 2h x 4l
    float acc[2][4] = {};
    const float* Wp = W + (n*H_ + h0)*D_;
    const float* Xp = X + (b*L  + l0)*D_;
    int xrow = tid >> 2;          // 0..63 (X staging l-row)
    int dq   = (tid & 3) * 4;     // 0,4,8,12
    int wrow = (tid & 127) >> 2;  // 0..31 (W staging h-row, threads 0..127)
    for (int d0 = 0; d0 < D_; d0 += 16) {
        float4 x4 = *(const float4*)(Xp + xrow*D_ + d0 + dq);
        float4 w4;
        if (tid < 128) w4 = *(const float4*)(Wp + wrow*D_ + d0 + dq);
        __syncthreads();
        Xs[dq+0][xrow] = x4.x; Xs[dq+1][xrow] = x4.y;
        Xs[dq+2][xrow] = x4.z; Xs[dq+3][xrow] = x4.w;
        if (tid < 128) {
            Ws[dq+0][wrow] = w4.x; Ws[dq+1][wrow] = w4.y;
            Ws[dq+2][wrow] = w4.z; Ws[dq+3][wrow] = w4.w;
        }
        __syncthreads();
        #pragma unroll
        for (int dd = 0; dd < 16; ++dd) {
            float a0 = Ws[dd][ty*2+0];
            float a1 = Ws[dd][ty*2+1];
            float4 b4 = *(const float4*)&Xs[dd][tx*4];
            float bv[4] = {b4.x, b4.y, b4.z, b4.w};
            #pragma unroll
            for (int j = 0; j < 4; ++j) {
                acc[0][j] = fmaf(a0, bv[j], acc[0][j]);
                acc[1][j] = fmaf(a1, bv[j], acc[1][j]);
            }
        }
    }
    float* Op = OUT + ((b*NH_ + n)*H_ + h0 + ty*2)*L + l0 + tx*4;
    #pragma unroll
    for (int i = 0; i < 2; ++i)
        *(float4*)(Op + i*L) = make_float4(acc[i][0], acc[i][1], acc[i][2], acc[i][3]);
}

// ============================================================================
// K2: scores + masked softmax.  (unchanged — near MUFU floor)
// Block = (b, n, 8 q-rows) x 256 k. 256 threads; thread = 4q x 2k.
// tanh via MUFU tanh.approx => 1 MUFU / element.
// ============================================================================
__global__ void __launch_bounds__(256) score_softmax_kernel(
    const float* __restrict__ wv, const int* __restrict__ valid_lens)
{
    __shared__ float Ks[16][LK_];   // [h][k]
    __shared__ float Qs[16][8];     // [h][q]
    __shared__ float Wvs[16];
    __shared__ float redA[2][4][4];
    __shared__ float redB[2][4][4];

    int b = blockIdx.z, n = blockIdx.y;
    int q0 = blockIdx.x * 8;
    int tid = threadIdx.x;
    int qg = tid >> 7;      // 0..1
    int kg = tid & 127;     // 0..127
    int ks = kg * 2;
    int valid = valid_lens[b];
    bool active = ks < valid;
    const float* KHp = g_KH + ((b*NH_ + n)*H_)*LK_;
    const float* QHp = g_QH + ((b*NH_ + n)*H_)*LQ_ + q0;
    const float* wvp = wv + n*H_;

    float acc[4][2] = {};

    for (int h0 = 0; h0 < H_; h0 += 16) {
        __syncthreads();
        #pragma unroll
        for (int t = 0; t < 4; ++t) {               // stage K chunk [16h][256k]
            int idx = tid + t*256;
            int r = idx >> 6, c4 = idx & 63;
            *(float4*)&Ks[r][c4*4] = *(const float4*)(KHp + (h0+r)*LK_ + c4*4);
        }
        if (tid < 128) Qs[tid >> 3][tid & 7] = QHp[(h0 + (tid >> 3))*LQ_ + (tid & 7)];
        if (tid < 16) Wvs[tid] = wvp[h0 + tid];
        __syncthreads();

        if (active) {
            #pragma unroll
            for (int dd = 0; dd < 16; ++dd) {
                float2 k2 = *(const float2*)&Ks[dd][ks];
                float4 q4 = *(const float4*)&Qs[dd][qg*4];
                float w = Wvs[dd];
                float kv[2] = {k2.x, k2.y};
                float qv[4] = {q4.x, q4.y, q4.z, q4.w};
                #pragma unroll
                for (int i = 0; i < 4; ++i)
                    #pragma unroll
                    for (int j = 0; j < 2; ++j) {
                        float th;
                        asm("tanh.approx.f32 %0, %1;" : "=f"(th) : "f"(qv[i] + kv[j]));
                        acc[i][j] = fmaf(w, th, acc[i][j]);
                    }
            }
        }
    }

    // ---- softmax over k (128 threads = 4 warps per q-group) ----
    float m[4];
    #pragma unroll
    for (int i = 0; i < 4; ++i) {
        float mm = -1e30f;
        #pragma unroll
        for (int j = 0; j < 2; ++j)
            if (ks + j < valid) mm = fmaxf(mm, acc[i][j]);
        m[i] = mm;
    }
    #pragma unroll
    for (int off = 16; off; off >>= 1)
        #pragma unroll
        for (int i = 0; i < 4; ++i)
            m[i] = fmaxf(m[i], __shfl_xor_sync(0xffffffffu, m[i], off));
    int w4 = (tid >> 5) & 3;
    if ((tid & 31) == 0)
        #pragma unroll
        for (int i = 0; i < 4; ++i) redA[qg][w4][i] = m[i];
    __syncthreads();
    #pragma unroll
    for (int i = 0; i < 4; ++i)
        m[i] = fmaxf(fmaxf(redA[qg][0][i], redA[qg][1][i]),
                     fmaxf(redA[qg][2][i], redA[qg][3][i]));

    float p[4][2], s[4] = {0.f, 0.f, 0.f, 0.f};
    #pragma unroll
    for (int i = 0; i < 4; ++i)
        #pragma unroll
        for (int j = 0; j < 2; ++j) {
            float e;
            asm("ex2.approx.f32 %0, %1;" : "=f"(e) : "f"((acc[i][j] - m[i]) * L2E));
            bool v = (ks + j) < valid;
            p[i][j] = v ? e : 0.0f;
            s[i] += p[i][j];
        }
    #pragma unroll
    for (int off = 16; off; off >>= 1)
        #pragma unroll
        for (int i = 0; i < 4; ++i)
            s[i] += __shfl_xor_sync(0xffffffffu, s[i], off);
    if ((tid & 31) == 0)
        #pragma unroll
        for (int i = 0; i < 4; ++i) redB[qg][w4][i] = s[i];
    __syncthreads();

    float* Ap = g_ATTN + ((b*NH_ + n)*LQ_ + q0 + qg*4)*LK_ + ks;
    #pragma unroll
    for (int i = 0; i < 4; ++i) {
        float inv = 1.0f / (redB[qg][0][i] + redB[qg][1][i] +
                            redB[qg][2][i] + redB[qg][3][i]);
        *(float2*)(Ap + i*LK_) = make_float2(p[i][0]*inv, p[i][1]*inv);
    }
}

// ============================================================================
// K3: out_heads = attn @ V, stored directly in concat layout [b][q][n*D+d].
// 16q x 64d tile per block, BK=32, 256 threads, thread = 1q x 4d.
// grid (8, 2, 32) = 512 blocks. k-loop bounded by valid_len.
// ============================================================================
__global__ void __launch_bounds__(256) av_kernel(
    const float* __restrict__ V, const int* __restrict__ valid_lens)
{
    __shared__ float As[32][17];   // [k][q] (scalar-read only)
    __shared__ float Bs[32][64];   // [k][d] (float4, 256B rows)
    int bz = blockIdx.z; int b = bz >> 3, n = bz & 7;
    int q0 = blockIdx.x * 16, d0 = blockIdx.y * 64;
    int valid = valid_lens[b];
    int kend = (valid + 31) & ~31;
    int tid = threadIdx.x;                  // 256
    int ty = tid >> 4, tx = tid & 15;       // 16 x 16; thread = 1q x 4d
    float acc[4] = {};
    const float* Ap = g_ATTN + ((b*NH_ + n)*LQ_ + q0)*LK_;
    const float* Vp = V + (b*LK_)*D_ + d0;
    int qrow = (tid & 127) >> 3;    // 0..15 (A staging, threads 0..127)
    int kq   = (tid & 7) * 4;       // 0..28
    for (int k0 = 0; k0 < kend; k0 += 32) {
        __syncthreads();
        if (tid < 128) {
            float4 a = *(const float4*)(Ap + qrow*LK_ + k0 + kq);
            As[kq+0][qrow] = a.x; As[kq+1][qrow] = a.y;
            As[kq+2][qrow] = a.z; As[kq+3][qrow] = a.w;
        }
        #pragma unroll
        for (int t = 0; t < 2; ++t) {
            int idx = tid + t*256;
            int r = idx >> 4, c4 = idx & 15;
            *(float4*)&Bs[r][c4*4] = *(const float4*)(Vp + (k0+r)*D_ + c4*4);
        }
        __syncthreads();
        #pragma unroll
        for (int kk = 0; kk < 32; ++kk) {
            float a0 = As[kk][ty];
            float4 b4 = *(const float4*)&Bs[kk][tx*4];
            acc[0] = fmaf(a0, b4.x, acc[0]);
            acc[1] = fmaf(a0, b4.y, acc[1]);
            acc[2] = fmaf(a0, b4.z, acc[2]);
            acc[3] = fmaf(a0, b4.w, acc[3]);
        }
    }
    float* Cp = g_CONCAT + (b*LQ_ + q0 + ty)*(NH_*D_) + n*D_ + d0 + tx*4;
    *(float4*)Cp = make_float4(acc[0], acc[1], acc[2], acc[3]);
}

// ============================================================================
// K4a: split-K output projection partials.
// partial[s][r][h] = sum_{j in split s} concat[r][j] * Wo[h][j]
// grid (8 row-tiles, 4 h-tiles, 16 splits) = 512 blocks, 256 threads.
// Tile: 64 rows x 32 h, K-chunk = 64 per split, BK=16 -> 4 iterations.
// Thread = 2 rows x 4 h. Bs rows 144B (16B multiple) for aligned float4 reads.
// ============================================================================
__global__ void __launch_bounds__(256) outproj_split_kernel(
    const float* __restrict__ Wo)
{
    __shared__ float As[16][65];   // [j][row] (scalar-read only)
    __shared__ float Bs[16][36];   // [j][h]   (float4-read, 16B-aligned rows)
    int r0 = blockIdx.x * 64;
    int h0 = blockIdx.y * 32;
    int split = blockIdx.z;
    int j0base = split * (NH_*D_ / NSPLIT);   // 64-wide K chunk
    int tid = threadIdx.x;          // 256
    int ry = tid >> 3;              // 0..31 -> row pair
    int tx = tid & 7;               // -> h group of 4
    const float* Cc = g_CONCAT;
    float acc[2][4] = {};

    int arow = tid >> 2;            // 0..63 (A staging row)
    int ajq  = (tid & 3) * 4;       // j offset 0,4,8,12
    int bhr  = (tid & 127) >> 2;    // 0..31 (B staging h), threads 0..127 only
    int bjq  = (tid & 3) * 4;

    #pragma unroll
    for (int jc = 0; jc < 4; ++jc) {
        int j0 = j0base + jc * 16;
        __syncthreads();
        {
            float4 a = *(const float4*)(Cc + (r0+arow)*(NH_*D_) + j0 + ajq);
            As[ajq+0][arow] = a.x; As[ajq+1][arow] = a.y;
            As[ajq+2][arow] = a.z; As[ajq+3][arow] = a.w;
        }
        if (tid < 128) {
            float4 w = *(const float4*)(Wo + (h0+bhr)*(NH_*D_) + j0 + bjq);
            Bs[bjq+0][bhr] = w.x; Bs[bjq+1][bhr] = w.y;
            Bs[bjq+2][bhr] = w.z; Bs[bjq+3][bhr] = w.w;
        }
        __syncthreads();
        #pragma unroll
        for (int jj = 0; jj < 16; ++jj) {
            float a0 = As[jj][ry*2+0];
            float a1 = As[jj][ry*2+1];
            float4 b4 = *(const float4*)&Bs[jj][tx*4];
            float bv[4] = {b4.x, b4.y, b4.z, b4.w};
            #pragma unroll
            for (int j = 0; j < 4; ++j) {
                acc[0][j] = fmaf(a0, bv[j], acc[0][j]);
                acc[1][j] = fmaf(a1, bv[j], acc[1][j]);
            }
        }
    }
    float* Pp = g_PART + ((split*(B_*LQ_)) + r0 + ry*2)*H_ + h0 + tx*4;
    #pragma unroll
    for (int i = 0; i < 2; ++i)
        *(float4*)(Pp + i*H_) = make_float4(acc[i][0], acc[i][1], acc[i][2], acc[i][3]);
}

// ============================================================================
// K4b: reduce splits + bias.  out[r][h] = bias[h] + sum_s partial[s][r][h]
// 16384 threads, float4 each. Deterministic (fixed summation order).
// ============================================================================
__global__ void __launch_bounds__(256) outproj_reduce_kernel(
    const float* __restrict__ bias, float* __restrict__ out)
{
    int idx = blockIdx.x * 256 + threadIdx.x;     // float4 index over 512*128/4
    int h4 = (idx & (H_/4 - 1)) * 4;
    float4 a = *(const float4*)(bias + h4);
    #pragma unroll
    for (int s = 0; s < NSPLIT; ++s) {
        float4 p = *(const float4*)(g_PART + s*(B_*LQ_*H_) + idx*4);
        a.x += p.x; a.y += p.y; a.z += p.z; a.w += p.w;
    }
    *(float4*)((float*)out + idx*4) = a;
}

// ============================================================================
extern "C" void kernel_launch(void* const* d_in, const int* in_sizes, int n_in,
                              void* d_out, int out_size)
{
    const float* queries    = (const float*)d_in[0];
    const float* keys       = (const float*)d_in[1];
    const float* values     = (const float*)d_in[2];
    const int*   valid_lens = (const int*)  d_in[3];
    const float* Wq         = (const float*)d_in[4];
    const float* Wk         = (const float*)d_in[5];
    const float* wv         = (const float*)d_in[6];
    const float* Wo_w       = (const float*)d_in[7];
    const float* Wo_b       = (const float*)d_in[8];
    float* out = (float*)d_out;

    proj_kernel<<<dim3(4, 4, 64), 256>>>(queries, keys, Wq, Wk);
    score_softmax_kernel<<<dim3(LQ_/8, NH_, B_), 256>>>(wv, valid_lens);
    av_kernel<<<dim3(LQ_/16, D_/64, B_*NH_), 256>>>(values, valid_lens);
    outproj_split_kernel<<<dim3(8, 4, NSPLIT), 256>>>(Wo_w);
    outproj_reduce_kernel<<<dim3(B_*LQ_*H_/4/256), 256>>>(Wo_b, out);
}

// round 7
// speedup vs baseline: 1.1145x; 1.1145x over previous
#include <cuda_runtime.h>

#define B_   4
#define LQ_  128
#define LK_  256
#define D_   128
#define H_   128
#define NH_  8

#define L2E 1.4426950408889634f  // log2(e) for softmax exp

#define NSPLIT 16                // K-splits for the output projection

// ---- scratch (static device memory; no allocation) ----
__device__ __align__(16) float g_QH[B_*NH_*H_*LQ_];      // [b][n][h][q]
__device__ __align__(16) float g_KH[B_*NH_*H_*LK_];      // [b][n][h][k]
__device__ __align__(16) float g_CONCAT[B_*LQ_*NH_*D_];  // [b][q][n*D+d]
__device__ __align__(16) float g_PART[NSPLIT*B_*LQ_*H_]; // split-K partials

// ============================================================================
// K1: merged Q+K per-head projections  (round-5 shape: best measured)
// OUT[b][n][h][l] = sum_d W[n][h][d] * X[b][l][d]
// 64x64 tile, BK=16, 256 threads, 4x4 per thread.
// grid = (4, 2, 64); z<32 -> K-proj, z>=32 -> Q-proj (extra x-blocks exit).
// ============================================================================
__global__ void __launch_bounds__(256) proj_kernel(
    const float* __restrict__ Q, const float* __restrict__ K,
    const float* __restrict__ Wq, const float* __restrict__ Wk)
{
    int zz = blockIdx.z;
    bool isq = zz >= 32;
    int bn = isq ? (zz - 32) : zz;
    int b = bn >> 3, n = bn & 7;
    int L = isq ? LQ_ : LK_;
    int l0 = blockIdx.x * 64;
    if (l0 >= L) return;                        // uniform per block
    const float* X = isq ? Q : K;
    const float* W = isq ? Wq : Wk;
    float* OUT = isq ? g_QH : g_KH;

    __shared__ float Ws[16][64];   // [d][h]
    __shared__ float Xs[16][64];   // [d][l]
    int h0 = blockIdx.y * 64;
    int tid = threadIdx.x;                 // 256
    int ty = tid >> 4, tx = tid & 15;      // 16x16
    float acc[4][4] = {};
    const float* Wp = W + (n*H_ + h0)*D_;
    const float* Xp = X + (b*L  + l0)*D_;
    int row = tid >> 2;          // 0..63
    int dq  = (tid & 3) * 4;     // 0,4,8,12
    for (int d0 = 0; d0 < D_; d0 += 16) {
        float4 w4 = *(const float4*)(Wp + row*D_ + d0 + dq);
        float4 x4 = *(const float4*)(Xp + row*D_ + d0 + dq);
        __syncthreads();
        Ws[dq+0][row] = w4.x; Ws[dq+1][row] = w4.y; Ws[dq+2][row] = w4.z; Ws[dq+3][row] = w4.w;
        Xs[dq+0][row] = x4.x; Xs[dq+1][row] = x4.y; Xs[dq+2][row] = x4.z; Xs[dq+3][row] = x4.w;
        __syncthreads();
        #pragma unroll
        for (int dd = 0; dd < 16; ++dd) {
            float4 a4 = *(const float4*)&Ws[dd][ty*4];
            float4 b4 = *(const float4*)&Xs[dd][tx*4];
            float av[4] = {a4.x, a4.y, a4.z, a4.w};
            float bv[4] = {b4.x, b4.y, b4.z, b4.w};
            #pragma unroll
            for (int i = 0; i < 4; ++i)
                #pragma unroll
                for (int j = 0; j < 4; ++j)
                    acc[i][j] = fmaf(av[i], bv[j], acc[i][j]);
        }
    }
    float* Op = OUT + ((b*NH_ + n)*H_ + h0 + ty*4)*L + l0 + tx*4;
    #pragma unroll
    for (int i = 0; i < 4; ++i)
        *(float4*)(Op + i*L) = make_float4(acc[i][0], acc[i][1], acc[i][2], acc[i][3]);
}

// ============================================================================
// K2: FUSED scores + masked softmax + attn@V.
// Block = (b, n, 8 q-rows). Phase 1 (score+softmax): thread = 4q x 2k over all
// 256 k; attn kept in smem (not written to global). Phase 2 (attn@V): thread =
// 1q x 4d; V staged in 32k x 128d smem chunks; writes concat layout directly.
// tanh via MUFU tanh.approx. k >= valid_len contributes exactly 0.
// ============================================================================
__global__ void __launch_bounds__(256) score_av_kernel(
    const float* __restrict__ wv, const int* __restrict__ valid_lens,
    const float* __restrict__ V)
{
    __shared__ float Ks[16][LK_];      // [h][k]  16KB
    __shared__ float Qs[16][8];        // [h][q]
    __shared__ float Wvs[16];
    __shared__ float redA[2][4][4];
    __shared__ float redB[2][4][4];
    __shared__ float attn_s[8][LK_];   // [q][k]   8KB
    __shared__ float Vs[32][D_];       // [k][d]  16KB (float4-read, 512B rows)

    int b = blockIdx.z, n = blockIdx.y;
    int q0 = blockIdx.x * 8;
    int tid = threadIdx.x;
    int qg = tid >> 7;      // 0..1
    int kg = tid & 127;     // 0..127
    int ks = kg * 2;
    int valid = valid_lens[b];
    bool active = ks < valid;
    const float* KHp = g_KH + ((b*NH_ + n)*H_)*LK_;
    const float* QHp = g_QH + ((b*NH_ + n)*H_)*LQ_ + q0;
    const float* wvp = wv + n*H_;

    float acc[4][2] = {};

    for (int h0 = 0; h0 < H_; h0 += 16) {
        __syncthreads();
        #pragma unroll
        for (int t = 0; t < 4; ++t) {               // stage K chunk [16h][256k]
            int idx = tid + t*256;
            int r = idx >> 6, c4 = idx & 63;
            *(float4*)&Ks[r][c4*4] = *(const float4*)(KHp + (h0+r)*LK_ + c4*4);
        }
        if (tid < 128) Qs[tid >> 3][tid & 7] = QHp[(h0 + (tid >> 3))*LQ_ + (tid & 7)];
        if (tid < 16) Wvs[tid] = wvp[h0 + tid];
        __syncthreads();

        if (active) {
            #pragma unroll
            for (int dd = 0; dd < 16; ++dd) {
                float2 k2 = *(const float2*)&Ks[dd][ks];
                float4 q4 = *(const float4*)&Qs[dd][qg*4];
                float w = Wvs[dd];
                float kv[2] = {k2.x, k2.y};
                float qv[4] = {q4.x, q4.y, q4.z, q4.w};
                #pragma unroll
                for (int i = 0; i < 4; ++i)
                    #pragma unroll
                    for (int j = 0; j < 2; ++j) {
                        float th;
                        asm("tanh.approx.f32 %0, %1;" : "=f"(th) : "f"(qv[i] + kv[j]));
                        acc[i][j] = fmaf(w, th, acc[i][j]);
                    }
            }
        }
    }

    // ---- softmax over k (4 warps per q-group) ----
    float m[4];
    #pragma unroll
    for (int i = 0; i < 4; ++i) {
        float mm = -1e30f;
        #pragma unroll
        for (int j = 0; j < 2; ++j)
            if (ks + j < valid) mm = fmaxf(mm, acc[i][j]);
        m[i] = mm;
    }
    #pragma unroll
    for (int off = 16; off; off >>= 1)
        #pragma unroll
        for (int i = 0; i < 4; ++i)
            m[i] = fmaxf(m[i], __shfl_xor_sync(0xffffffffu, m[i], off));
    int w4 = (tid >> 5) & 3;
    if ((tid & 31) == 0)
        #pragma unroll
        for (int i = 0; i < 4; ++i) redA[qg][w4][i] = m[i];
    __syncthreads();
    #pragma unroll
    for (int i = 0; i < 4; ++i)
        m[i] = fmaxf(fmaxf(redA[qg][0][i], redA[qg][1][i]),
                     fmaxf(redA[qg][2][i], redA[qg][3][i]));

    float p[4][2], s[4] = {0.f, 0.f, 0.f, 0.f};
    #pragma unroll
    for (int i = 0; i < 4; ++i)
        #pragma unroll
        for (int j = 0; j < 2; ++j) {
            float e;
            asm("ex2.approx.f32 %0, %1;" : "=f"(e) : "f"((acc[i][j] - m[i]) * L2E));
            bool v = (ks + j) < valid;
            p[i][j] = v ? e : 0.0f;
            s[i] += p[i][j];
        }
    #pragma unroll
    for (int off = 16; off; off >>= 1)
        #pragma unroll
        for (int i = 0; i < 4; ++i)
            s[i] += __shfl_xor_sync(0xffffffffu, s[i], off);
    if ((tid & 31) == 0)
        #pragma unroll
        for (int i = 0; i < 4; ++i) redB[qg][w4][i] = s[i];
    __syncthreads();

    #pragma unroll
    for (int i = 0; i < 4; ++i) {
        float inv = 1.0f / (redB[qg][0][i] + redB[qg][1][i] +
                            redB[qg][2][i] + redB[qg][3][i]);
        *(float2*)&attn_s[qg*4+i][ks] = make_float2(p[i][0]*inv, p[i][1]*inv);
    }
    // (attn_s fully written for k in [0,256): zeros beyond valid)

    // ---- Phase 2: out = attn_s @ V[b], thread = 1q x 4d ----
    int ty = tid >> 5;          // q row 0..7
    int tx = tid & 31;          // d group of 4
    float oa[4] = {};
    int kend = (valid + 31) & ~31;
    const float* Vp = V + (b*LK_)*D_;
    for (int k0 = 0; k0 < kend; k0 += 32) {
        __syncthreads();        // also orders attn_s writes on first iter
        #pragma unroll
        for (int t = 0; t < 4; ++t) {   // stage V chunk [32k][128d]
            int idx = tid + t*256;
            int r = idx >> 5, c4 = idx & 31;
            *(float4*)&Vs[r][c4*4] = *(const float4*)(Vp + (k0+r)*D_ + c4*4);
        }
        __syncthreads();
        #pragma unroll
        for (int kk = 0; kk < 32; ++kk) {
            float a = attn_s[ty][k0+kk];          // broadcast within warp
            float4 v4 = *(const float4*)&Vs[kk][tx*4];
            oa[0] = fmaf(a, v4.x, oa[0]);
            oa[1] = fmaf(a, v4.y, oa[1]);
            oa[2] = fmaf(a, v4.z, oa[2]);
            oa[3] = fmaf(a, v4.w, oa[3]);
        }
    }
    float* Cp = g_CONCAT + (b*LQ_ + q0 + ty)*(NH_*D_) + n*D_ + tx*4;
    *(float4*)Cp = make_float4(oa[0], oa[1], oa[2], oa[3]);
}

// ============================================================================
// K3a: split-K output projection partials.  (NSPLIT=16, best measured)
// partial[s][r][h] = sum_{j in split s} concat[r][j] * Wo[h][j]
// grid (8 row-tiles, 4 h-tiles, 16 splits) = 512 blocks, 256 threads.
// Tile: 64 rows x 32 h, K-chunk = 64 per split, BK=16 -> 4 iterations.
// Thread = 2 rows x 4 h. Bs rows 144B (16B multiple) for aligned float4 reads.
// ============================================================================
__global__ void __launch_bounds__(256) outproj_split_kernel(
    const float* __restrict__ Wo)
{
    __shared__ float As[16][65];   // [j][row] (scalar-read only)
    __shared__ float Bs[16][36];   // [j][h]   (float4-read, 16B-aligned rows)
    int r0 = blockIdx.x * 64;
    int h0 = blockIdx.y * 32;
    int split = blockIdx.z;
    int j0base = split * (NH_*D_ / NSPLIT);   // 64-wide K chunk
    int tid = threadIdx.x;          // 256
    int ry = tid >> 3;              // 0..31 -> row pair
    int tx = tid & 7;               // -> h group of 4
    const float* Cc = g_CONCAT;
    float acc[2][4] = {};

    int arow = tid >> 2;            // 0..63 (A staging row)
    int ajq  = (tid & 3) * 4;       // j offset 0,4,8,12
    int bhr  = (tid & 127) >> 2;    // 0..31 (B staging h), threads 0..127 only
    int bjq  = (tid & 3) * 4;

    #pragma unroll
    for (int jc = 0; jc < 4; ++jc) {
        int j0 = j0base + jc * 16;
        __syncthreads();
        {
            float4 a = *(const float4*)(Cc + (r0+arow)*(NH_*D_) + j0 + ajq);
            As[ajq+0][arow] = a.x; As[ajq+1][arow] = a.y;
            As[ajq+2][arow] = a.z; As[ajq+3][arow] = a.w;
        }
        if (tid < 128) {
            float4 w = *(const float4*)(Wo + (h0+bhr)*(NH_*D_) + j0 + bjq);
            Bs[bjq+0][bhr] = w.x; Bs[bjq+1][bhr] = w.y;
            Bs[bjq+2][bhr] = w.z; Bs[bjq+3][bhr] = w.w;
        }
        __syncthreads();
        #pragma unroll
        for (int jj = 0; jj < 16; ++jj) {
            float a0 = As[jj][ry*2+0];
            float a1 = As[jj][ry*2+1];
            float4 b4 = *(const float4*)&Bs[jj][tx*4];
            float bv[4] = {b4.x, b4.y, b4.z, b4.w};
            #pragma unroll
            for (int j = 0; j < 4; ++j) {
                acc[0][j] = fmaf(a0, bv[j], acc[0][j]);
                acc[1][j] = fmaf(a1, bv[j], acc[1][j]);
            }
        }
    }
    float* Pp = g_PART + ((split*(B_*LQ_)) + r0 + ry*2)*H_ + h0 + tx*4;
    #pragma unroll
    for (int i = 0; i < 2; ++i)
        *(float4*)(Pp + i*H_) = make_float4(acc[i][0], acc[i][1], acc[i][2], acc[i][3]);
}

// ============================================================================
// K3b: reduce splits + bias.  out[r][h] = bias[h] + sum_s partial[s][r][h]
// 16384 threads, float4 each. Deterministic (fixed summation order).
// ============================================================================
__global__ void __launch_bounds__(256) outproj_reduce_kernel(
    const float* __restrict__ bias, float* __restrict__ out)
{
    int idx = blockIdx.x * 256 + threadIdx.x;     // float4 index over 512*128/4
    int h4 = (idx & (H_/4 - 1)) * 4;
    float4 a = *(const float4*)(bias + h4);
    #pragma unroll
    for (int s = 0; s < NSPLIT; ++s) {
        float4 p = *(const float4*)(g_PART + s*(B_*LQ_*H_) + idx*4);
        a.x += p.x; a.y += p.y; a.z += p.z; a.w += p.w;
    }
    *(float4*)((float*)out + idx*4) = a;
}

// ============================================================================
extern "C" void kernel_launch(void* const* d_in, const int* in_sizes, int n_in,
                              void* d_out, int out_size)
{
    const float* queries    = (const float*)d_in[0];
    const float* keys       = (const float*)d_in[1];
    const float* values     = (const float*)d_in[2];
    const int*   valid_lens = (const int*)  d_in[3];
    const float* Wq         = (const float*)d_in[4];
    const float* Wk         = (const float*)d_in[5];
    const float* wv         = (const float*)d_in[6];
    const float* Wo_w       = (const float*)d_in[7];
    const float* Wo_b       = (const float*)d_in[8];
    float* out = (float*)d_out;

    proj_kernel<<<dim3(4, 2, 64), 256>>>(queries, keys, Wq, Wk);
    score_av_kernel<<<dim3(LQ_/8, NH_, B_), 256>>>(wv, valid_lens, values);
    outproj_split_kernel<<<dim3(8, 4, NSPLIT), 256>>>(Wo_w);
    outproj_reduce_kernel<<<dim3(B_*LQ_*H_/4/256), 256>>>(Wo_b, out);
}

// round 9
// speedup vs baseline: 1.1219x; 1.0066x over previous
#include <cuda_runtime.h>
#include <cuda_fp16.h>

#define B_   4
#define LQ_  128
#define LK_  256
#define D_   128
#define H_   128
#define NH_  8

#define L2E 1.4426950408889634f  // log2(e) for softmax exp

#define NSPLIT 8                 // K-splits for the output projection

// ---- scratch (static device memory; no allocation) ----
__device__ __align__(16) float  g_QH[B_*NH_*H_*LQ_];      // [b][n][h][q] fp32
__device__ __align__(16) __half g_KHh[B_*NH_*H_*LK_];     // [b][n][h][k] fp16
__device__ __align__(16) float  g_CONCAT[B_*LQ_*NH_*D_];  // [b][q][n*D+d]
__device__ __align__(16) float  g_PART[NSPLIT*B_*LQ_*H_]; // split-K partials

// ============================================================================
// K1: merged Q+K per-head projections
// OUT[b][n][h][l] = sum_d W[n][h][d] * X[b][l][d]
// 64x64 tile, BK=16, 256 threads, 4x4 per thread.
// grid = (4, 2, 64); z<32 -> K-proj (fp16 out), z>=32 -> Q-proj (fp32 out).
// ============================================================================
__global__ void __launch_bounds__(256) proj_kernel(
    const float* __restrict__ Q, const float* __restrict__ K,
    const float* __restrict__ Wq, const float* __restrict__ Wk)
{
    int zz = blockIdx.z;
    bool isq = zz >= 32;
    int bn = isq ? (zz - 32) : zz;
    int b = bn >> 3, n = bn & 7;
    int L = isq ? LQ_ : LK_;
    int l0 = blockIdx.x * 64;
    if (l0 >= L) return;                        // uniform per block
    const float* X = isq ? Q : K;
    const float* W = isq ? Wq : Wk;

    __shared__ float Ws[16][64];   // [d][h]
    __shared__ float Xs[16][64];   // [d][l]
    int h0 = blockIdx.y * 64;
    int tid = threadIdx.x;                 // 256
    int ty = tid >> 4, tx = tid & 15;      // 16x16
    float acc[4][4] = {};
    const float* Wp = W + (n*H_ + h0)*D_;
    const float* Xp = X + (b*L  + l0)*D_;
    int row = tid >> 2;          // 0..63
    int dq  = (tid & 3) * 4;     // 0,4,8,12
    for (int d0 = 0; d0 < D_; d0 += 16) {
        float4 w4 = *(const float4*)(Wp + row*D_ + d0 + dq);
        float4 x4 = *(const float4*)(Xp + row*D_ + d0 + dq);
        __syncthreads();
        Ws[dq+0][row] = w4.x; Ws[dq+1][row] = w4.y; Ws[dq+2][row] = w4.z; Ws[dq+3][row] = w4.w;
        Xs[dq+0][row] = x4.x; Xs[dq+1][row] = x4.y; Xs[dq+2][row] = x4.z; Xs[dq+3][row] = x4.w;
        __syncthreads();
        #pragma unroll
        for (int dd = 0; dd < 16; ++dd) {
            float4 a4 = *(const float4*)&Ws[dd][ty*4];
            float4 b4 = *(const float4*)&Xs[dd][tx*4];
            float av[4] = {a4.x, a4.y, a4.z, a4.w};
            float bv[4] = {b4.x, b4.y, b4.z, b4.w};
            #pragma unroll
            for (int i = 0; i < 4; ++i)
                #pragma unroll
                for (int j = 0; j < 4; ++j)
                    acc[i][j] = fmaf(av[i], bv[j], acc[i][j]);
        }
    }
    if (isq) {
        float* Op = g_QH + ((b*NH_ + n)*H_ + h0 + ty*4)*L + l0 + tx*4;
        #pragma unroll
        for (int i = 0; i < 4; ++i)
            *(float4*)(Op + i*L) = make_float4(acc[i][0], acc[i][1], acc[i][2], acc[i][3]);
    } else {
        __half* Op = g_KHh + ((b*NH_ + n)*H_ + h0 + ty*4)*LK_ + l0 + tx*4;
        #pragma unroll
        for (int i = 0; i < 4; ++i) {
            __half2 h01 = __floats2half2_rn(acc[i][0], acc[i][1]);
            __half2 h23 = __floats2half2_rn(acc[i][2], acc[i][3]);
            *(__half2*)(Op + i*LK_)     = h01;
            *(__half2*)(Op + i*LK_ + 2) = h23;
        }
    }
}

// ============================================================================
// K2: FUSED scores + masked softmax + attn@V.
// Block = (b, n, 8 q-rows). Phase 1: thread = 4q x 2k; the k-pair is a half2 —
// tanh.approx.f16x2 does 2 tanh per MUFU op; accumulate in fp32.
// Phase 2: thread = 1q x 4d over V chunks; writes concat layout directly.
// k >= valid_len contributes exactly 0 (softmax mask).
// ============================================================================
__global__ void __launch_bounds__(256) score_av_kernel(
    const float* __restrict__ wv, const int* __restrict__ valid_lens,
    const float* __restrict__ V)
{
    __shared__ __half Ks[16][LK_];     // [h][k] fp16  8KB
    __shared__ float Qs[16][8];        // [h][q]
    __shared__ float Wvs[16];
    __shared__ float redA[2][4][4];
    __shared__ float redB[2][4][4];
    __shared__ float attn_s[8][LK_];   // [q][k]   8KB
    __shared__ float Vs[32][D_];       // [k][d]  16KB

    int b = blockIdx.z, n = blockIdx.y;
    int q0 = blockIdx.x * 8;
    int tid = threadIdx.x;
    int qg = tid >> 7;      // 0..1
    int kg = tid & 127;     // 0..127
    int ks = kg * 2;
    int valid = valid_lens[b];
    bool active = ks < valid;
    const __half* KHp = g_KHh + ((b*NH_ + n)*H_)*LK_;
    const float*  QHp = g_QH  + ((b*NH_ + n)*H_)*LQ_ + q0;
    const float*  wvp = wv + n*H_;

    float acc[4][2] = {};

    for (int h0 = 0; h0 < H_; h0 += 16) {
        __syncthreads();
        #pragma unroll
        for (int t = 0; t < 2; ++t) {               // stage K chunk [16h][256k] fp16
            int idx = tid + t*256;                  // 0..511 uint4 (8 halves each)
            int r = idx >> 5, c = idx & 31;
            *(uint4*)&Ks[r][c*8] = *(const uint4*)(KHp + (h0+r)*LK_ + c*8);
        }
        if (tid < 128) Qs[tid >> 3][tid & 7] = QHp[(h0 + (tid >> 3))*LQ_ + (tid & 7)];
        if (tid < 16) Wvs[tid] = wvp[h0 + tid];
        __syncthreads();

        if (active) {
            #pragma unroll
            for (int dd = 0; dd < 16; ++dd) {
                unsigned k2u = *(const unsigned*)&Ks[dd][ks];
                float4 q4 = *(const float4*)&Qs[dd][qg*4];
                float w = Wvs[dd];
                float qv[4] = {q4.x, q4.y, q4.z, q4.w};
                #pragma unroll
                for (int i = 0; i < 4; ++i) {
                    unsigned qh, su, tu;
                    asm("cvt.rn.f16x2.f32 %0, %1, %2;" : "=r"(qh) : "f"(qv[i]), "f"(qv[i]));
                    asm("add.rn.f16x2 %0, %1, %2;"     : "=r"(su) : "r"(qh), "r"(k2u));
                    asm("tanh.approx.f16x2 %0, %1;"    : "=r"(tu) : "r"(su));
                    __half2 th = *reinterpret_cast<__half2*>(&tu);
                    float2 f = __half22float2(th);
                    acc[i][0] = fmaf(w, f.x, acc[i][0]);
                    acc[i][1] = fmaf(w, f.y, acc[i][1]);
                }
            }
        }
    }

    // ---- softmax over k (4 warps per q-group) ----
    float m[4];
    #pragma unroll
    for (int i = 0; i < 4; ++i) {
        float mm = -1e30f;
        #pragma unroll
        for (int j = 0; j < 2; ++j)
            if (ks + j < valid) mm = fmaxf(mm, acc[i][j]);
        m[i] = mm;
    }
    #pragma unroll
    for (int off = 16; off; off >>= 1)
        #pragma unroll
        for (int i = 0; i < 4; ++i)
            m[i] = fmaxf(m[i], __shfl_xor_sync(0xffffffffu, m[i], off));
    int w4 = (tid >> 5) & 3;
    if ((tid & 31) == 0)
        #pragma unroll
        for (int i = 0; i < 4; ++i) redA[qg][w4][i] = m[i];
    __syncthreads();
    #pragma unroll
    for (int i = 0; i < 4; ++i)
        m[i] = fmaxf(fmaxf(redA[qg][0][i], redA[qg][1][i]),
                     fmaxf(redA[qg][2][i], redA[qg][3][i]));

    float p[4][2], s[4] = {0.f, 0.f, 0.f, 0.f};
    #pragma unroll
    for (int i = 0; i < 4; ++i)
        #pragma unroll
        for (int j = 0; j < 2; ++j) {
            float e;
            asm("ex2.approx.f32 %0, %1;" : "=f"(e) : "f"((acc[i][j] - m[i]) * L2E));
            bool v = (ks + j) < valid;
            p[i][j] = v ? e : 0.0f;
            s[i] += p[i][j];
        }
    #pragma unroll
    for (int off = 16; off; off >>= 1)
        #pragma unroll
        for (int i = 0; i < 4; ++i)
            s[i] += __shfl_xor_sync(0xffffffffu, s[i], off);
    if ((tid & 31) == 0)
        #pragma unroll
        for (int i = 0; i < 4; ++i) redB[qg][w4][i] = s[i];
    __syncthreads();

    #pragma unroll
    for (int i = 0; i < 4; ++i) {
        float inv = 1.0f / (redB[qg][0][i] + redB[qg][1][i] +
                            redB[qg][2][i] + redB[qg][3][i]);
        *(float2*)&attn_s[qg*4+i][ks] = make_float2(p[i][0]*inv, p[i][1]*inv);
    }
    // (attn_s fully written for k in [0,256): zeros beyond valid)

    // ---- Phase 2: out = attn_s @ V[b], thread = 1q x 4d ----
    int ty = tid >> 5;          // q row 0..7
    int tx = tid & 31;          // d group of 4
    float oa[4] = {};
    int kend = (valid + 31) & ~31;
    const float* Vp = V + (b*LK_)*D_;
    for (int k0 = 0; k0 < kend; k0 += 32) {
        __syncthreads();        // also orders attn_s writes on first iter
        #pragma unroll
        for (int t = 0; t < 4; ++t) {   // stage V chunk [32k][128d]
            int idx = tid + t*256;
            int r = idx >> 5, c4 = idx & 31;
            *(float4*)&Vs[r][c4*4] = *(const float4*)(Vp + (k0+r)*D_ + c4*4);
        }
        __syncthreads();
        #pragma unroll
        for (int kk = 0; kk < 32; ++kk) {
            float a = attn_s[ty][k0+kk];          // broadcast within warp
            float4 v4 = *(const float4*)&Vs[kk][tx*4];
            oa[0] = fmaf(a, v4.x, oa[0]);
            oa[1] = fmaf(a, v4.y, oa[1]);
            oa[2] = fmaf(a, v4.z, oa[2]);
            oa[3] = fmaf(a, v4.w, oa[3]);
        }
    }
    float* Cp = g_CONCAT + (b*LQ_ + q0 + ty)*(NH_*D_) + n*D_ + tx*4;
    *(float4*)Cp = make_float4(oa[0], oa[1], oa[2], oa[3]);
}

// ============================================================================
// K3a: split-K output projection partials.
// partial[s][r][h] = sum_{j in split s} concat[r][j] * Wo[h][j]
// grid (8 row-tiles, 4 h-tiles, 8 splits), 256 threads.
// Tile: 64 rows x 32 h, K-chunk = 128 per split, BK=16 -> 8 iterations.
// Thread = 2 rows x 4 h. Bs rows 144B (16B multiple) for aligned float4 reads.
// ============================================================================
__global__ void __launch_bounds__(256) outproj_split_kernel(
    const float* __restrict__ Wo)
{
    __shared__ float As[16][65];   // [j][row] (scalar-read only)
    __shared__ float Bs[16][36];   // [j][h]   (float4-read, 16B-aligned rows)
    int r0 = blockIdx.x * 64;
    int h0 = blockIdx.y * 32;
    int split = blockIdx.z;
    int j0base = split * (NH_*D_ / NSPLIT);   // 128-wide K chunk
    int tid = threadIdx.x;          // 256
    int ry = tid >> 3;              // 0..31 -> row pair
    int tx = tid & 7;               // -> h group of 4
    const float* Cc = g_CONCAT;
    float acc[2][4] = {};

    int arow = tid >> 2;            // 0..63 (A staging row)
    int ajq  = (tid & 3) * 4;       // j offset 0,4,8,12
    int bhr  = (tid & 127) >> 2;    // 0..31 (B staging h), threads 0..127 only
    int bjq  = (tid & 3) * 4;

    #pragma unroll
    for (int jc = 0; jc < 8; ++jc) {
        int j0 = j0base + jc * 16;
        __syncthreads();
        {
            float4 a = *(const float4*)(Cc + (r0+arow)*(NH_*D_) + j0 + ajq);
            As[ajq+0][arow] = a.x; As[ajq+1][arow] = a.y;
            As[ajq+2][arow] = a.z; As[ajq+3][arow] = a.w;
        }
        if (tid < 128) {
            float4 w = *(const float4*)(Wo + (h0+bhr)*(NH_*D_) + j0 + bjq);
            Bs[bjq+0][bhr] = w.x; Bs[bjq+1][bhr] = w.y;
            Bs[bjq+2][bhr] = w.z; Bs[bjq+3][bhr] = w.w;
        }
        __syncthreads();
        #pragma unroll
        for (int jj = 0; jj < 16; ++jj) {
            float a0 = As[jj][ry*2+0];
            float a1 = As[jj][ry*2+1];
            float4 b4 = *(const float4*)&Bs[jj][tx*4];
            float bv[4] = {b4.x, b4.y, b4.z, b4.w};
            #pragma unroll
            for (int j = 0; j < 4; ++j) {
                acc[0][j] = fmaf(a0, bv[j], acc[0][j]);
                acc[1][j] = fmaf(a1, bv[j], acc[1][j]);
            }
        }
    }
    float* Pp = g_PART + ((split*(B_*LQ_)) + r0 + ry*2)*H_ + h0 + tx*4;
    #pragma unroll
    for (int i = 0; i < 2; ++i)
        *(float4*)(Pp + i*H_) = make_float4(acc[i][0], acc[i][1], acc[i][2], acc[i][3]);
}

// ============================================================================
// K3b: reduce splits + bias.  out[r][h] = bias[h] + sum_s partial[s][r][h]
// 16384 threads, float4 each. Deterministic (fixed summation order).
// ============================================================================
__global__ void __launch_bounds__(256) outproj_reduce_kernel(
    const float* __restrict__ bias, float* __restrict__ out)
{
    int idx = blockIdx.x * 256 + threadIdx.x;     // float4 index over 512*128/4
    int h4 = (idx & (H_/4 - 1)) * 4;
    float4 a = *(const float4*)(bias + h4);
    #pragma unroll
    for (int s = 0; s < NSPLIT; ++s) {
        float4 p = *(const float4*)(g_PART + s*(B_*LQ_*H_) + idx*4);
        a.x += p.x; a.y += p.y; a.z += p.z; a.w += p.w;
    }
    *(float4*)((float*)out + idx*4) = a;
}

// ============================================================================
extern "C" void kernel_launch(void* const* d_in, const int* in_sizes, int n_in,
                              void* d_out, int out_size)
{
    const float* queries    = (const float*)d_in[0];
    const float* keys       = (const float*)d_in[1];
    const float* values     = (const float*)d_in[2];
    const int*   valid_lens = (const int*)  d_in[3];
    const float* Wq         = (const float*)d_in[4];
    const float* Wk         = (const float*)d_in[5];
    const float* wv         = (const float*)d_in[6];
    const float* Wo_w       = (const float*)d_in[7];
    const float* Wo_b       = (const float*)d_in[8];
    float* out = (float*)d_out;

    proj_kernel<<<dim3(4, 2, 64), 256>>>(queries, keys, Wq, Wk);
    score_av_kernel<<<dim3(LQ_/8, NH_, B_), 256>>>(wv, valid_lens, values);
    outproj_split_kernel<<<dim3(8, 4, NSPLIT), 256>>>(Wo_w);
    outproj_reduce_kernel<<<dim3(B_*LQ_*H_/4/256), 256>>>(Wo_b, out);
}